// round 2
// baseline (speedup 1.0000x reference)
#include <cuda_runtime.h>
#include <cstdint>

// ============================================================================
// TiLinear: int8 GEMM (M=8192, IN=4096, OUT=4096) -> global range estimate ->
// pseudo-stochastic shift to int8 + block exponent. Output dtype: float32.
//
// Pipeline (graph-capturable, no allocs):
//   1. zero_max_kernel     : g_max = 0
//   2. pack_a / pack_b     : int32 containers -> packed int8 operands
//   3. gemm_s8_kernel      : mma.sync m16n8k32 s8 GEMM -> g_C32 + global max
//   4. epilogue_kernel     : psto-shift int32 -> int8 value, stored as float
//   5. tail_kernel         : exp_out (as float) after the activation block
// ============================================================================

#define M_DIM 8192
#define N_DIM 4096
#define K_DIM 4096
#define BITWIDTH 7

#define BM 128
#define BN 128
#define BK 128
#define KTILES (K_DIM / BK)

__device__ __align__(16) int8_t g_A8[(size_t)M_DIM * K_DIM];   // 32 MB
__device__ __align__(16) int8_t g_B8[(size_t)N_DIM * K_DIM];   // 16 MB
__device__ __align__(16) int    g_C32[(size_t)M_DIM * N_DIM];  // 128 MB
__device__ int g_max;

// ----------------------------------------------------------------------------
__global__ void zero_max_kernel() {
    if (threadIdx.x == 0) g_max = 0;
}

__global__ void __launch_bounds__(256) pack_a_kernel(const int* __restrict__ src, int n16) {
    int i = blockIdx.x * blockDim.x + threadIdx.x;
    if (i >= n16) return;
    const int4* s = (const int4*)src;
    uint32_t w[4];
#pragma unroll
    for (int j = 0; j < 4; ++j) {
        int4 v = s[(size_t)i * 4 + j];
        w[j] = (uint32_t)(v.x & 0xff) | ((uint32_t)(v.y & 0xff) << 8) |
               ((uint32_t)(v.z & 0xff) << 16) | ((uint32_t)(v.w & 0xff) << 24);
    }
    *(uint4*)(g_A8 + (size_t)i * 16) = make_uint4(w[0], w[1], w[2], w[3]);
}

__global__ void __launch_bounds__(256) pack_b_kernel(const int* __restrict__ src, int n16) {
    int i = blockIdx.x * blockDim.x + threadIdx.x;
    if (i >= n16) return;
    const int4* s = (const int4*)src;
    uint32_t w[4];
#pragma unroll
    for (int j = 0; j < 4; ++j) {
        int4 v = s[(size_t)i * 4 + j];
        w[j] = (uint32_t)(v.x & 0xff) | ((uint32_t)(v.y & 0xff) << 8) |
               ((uint32_t)(v.z & 0xff) << 16) | ((uint32_t)(v.w & 0xff) << 24);
    }
    *(uint4*)(g_B8 + (size_t)i * 16) = make_uint4(w[0], w[1], w[2], w[3]);
}

// ----------------------------------------------------------------------------
// SMEM swizzle: 128-byte rows, 8 x 16B chunks; chunk' = chunk ^ (row & 7).
__device__ __forceinline__ uint32_t swz_off(uint32_t row, uint32_t chunk) {
    return row * 128u + (((chunk ^ row) & 7u) << 4);
}

__device__ __forceinline__ void cp_async_16(uint32_t smem_addr, const void* gptr) {
    asm volatile("cp.async.cg.shared.global [%0], [%1], 16;\n" ::"r"(smem_addr), "l"(gptr));
}

__device__ __forceinline__ void fill_stage(int8_t* sa, int8_t* sb,
                                           const int8_t* gA, const int8_t* gB,
                                           int kt, int tid) {
#pragma unroll
    for (int p = 0; p < 4; ++p) {
        int idx = p * 256 + tid;
        int row = idx >> 3;
        int c   = idx & 7;
        uint32_t da = (uint32_t)__cvta_generic_to_shared(sa + swz_off(row, c));
        cp_async_16(da, gA + (size_t)row * K_DIM + kt * BK + c * 16);
        uint32_t db = (uint32_t)__cvta_generic_to_shared(sb + swz_off(row, c));
        cp_async_16(db, gB + (size_t)row * K_DIM + kt * BK + c * 16);
    }
    asm volatile("cp.async.commit_group;\n");
}

__global__ void __launch_bounds__(256) gemm_s8_kernel() {
    extern __shared__ __align__(16) int8_t smem[];
    int8_t* As = smem;                    // 2 stages x 16 KB
    int8_t* Bs = smem + 2 * BM * BK;      // 2 stages x 16 KB
    __shared__ int s_bmax;

    const int tid  = threadIdx.x;
    const int lane = tid & 31;
    const int warp = tid >> 5;
    const int wm   = warp >> 2;  // 0..1 : 64-row slab
    const int wn   = warp & 3;   // 0..3 : 32-col slab
    const int m0   = blockIdx.y * BM;
    const int n0   = blockIdx.x * BN;

    if (tid == 0) s_bmax = 0;

    int acc[4][4][4];
#pragma unroll
    for (int a = 0; a < 4; ++a)
#pragma unroll
        for (int b = 0; b < 4; ++b)
#pragma unroll
            for (int c = 0; c < 4; ++c) acc[a][b][c] = 0;

    const int8_t* gA = g_A8 + (size_t)m0 * K_DIM;
    const int8_t* gB = g_B8 + (size_t)n0 * K_DIM;

    fill_stage(As, Bs, gA, gB, 0, tid);

#pragma unroll 1
    for (int kt = 0; kt < KTILES; ++kt) {
        const int stage = kt & 1;
        if (kt + 1 < KTILES) {
            fill_stage(As + (stage ^ 1) * (BM * BK), Bs + (stage ^ 1) * (BN * BK),
                       gA, gB, kt + 1, tid);
            asm volatile("cp.async.wait_group 1;\n");
        } else {
            asm volatile("cp.async.wait_group 0;\n");
        }
        __syncthreads();

        const int8_t* sa = As + stage * (BM * BK);
        const int8_t* sb = Bs + stage * (BN * BK);

#pragma unroll
        for (int ks = 0; ks < 4; ++ks) {   // 4 x k32 within the 128-deep tile
            uint32_t afr[4][4];
#pragma unroll
            for (int mi = 0; mi < 4; ++mi) {
                int r = wm * 64 + mi * 16 + (lane & 15);
                int c = ks * 2 + (lane >> 4);
                uint32_t addr = (uint32_t)__cvta_generic_to_shared(sa + swz_off(r, c));
                asm volatile(
                    "ldmatrix.sync.aligned.m8n8.x4.shared.b16 {%0,%1,%2,%3}, [%4];\n"
                    : "=r"(afr[mi][0]), "=r"(afr[mi][1]),
                      "=r"(afr[mi][2]), "=r"(afr[mi][3])
                    : "r"(addr));
                // a0=(rows0-7,k0-15) a1=(rows8-15,k0-15) a2=(rows0-7,k16-31)
                // a3=(rows8-15,k16-31) == ldmatrix result order directly.
            }
            uint32_t bfr[4][2];
#pragma unroll
            for (int ni = 0; ni < 4; ++ni) {
                int r = wn * 32 + ni * 8 + (lane & 7);
                int c = ks * 2 + ((lane >> 3) & 1);
                uint32_t addr = (uint32_t)__cvta_generic_to_shared(sb + swz_off(r, c));
                asm volatile(
                    "ldmatrix.sync.aligned.m8n8.x2.shared.b16 {%0,%1}, [%2];\n"
                    : "=r"(bfr[ni][0]), "=r"(bfr[ni][1])
                    : "r"(addr));
            }
#pragma unroll
            for (int mi = 0; mi < 4; ++mi)
#pragma unroll
                for (int ni = 0; ni < 4; ++ni) {
                    asm volatile(
                        "mma.sync.aligned.m16n8k32.row.col.s32.s8.s8.s32 "
                        "{%0,%1,%2,%3}, {%4,%5,%6,%7}, {%8,%9}, {%0,%1,%2,%3};\n"
                        : "+r"(acc[mi][ni][0]), "+r"(acc[mi][ni][1]),
                          "+r"(acc[mi][ni][2]), "+r"(acc[mi][ni][3])
                        : "r"(afr[mi][0]), "r"(afr[mi][1]), "r"(afr[mi][2]), "r"(afr[mi][3]),
                          "r"(bfr[ni][0]), "r"(bfr[ni][1]));
                }
        }
        __syncthreads();
    }

    // Write int32 accumulators + reduce max|acc|
    int lmax = 0;
#pragma unroll
    for (int mi = 0; mi < 4; ++mi) {
#pragma unroll
        for (int ni = 0; ni < 4; ++ni) {
            int gm = m0 + wm * 64 + mi * 16 + (lane >> 2);
            int gn = n0 + wn * 32 + ni * 8 + (lane & 3) * 2;
            int c0 = acc[mi][ni][0], c1 = acc[mi][ni][1];
            int c2 = acc[mi][ni][2], c3 = acc[mi][ni][3];
            *(int2*)&g_C32[(size_t)gm * N_DIM + gn]       = make_int2(c0, c1);
            *(int2*)&g_C32[(size_t)(gm + 8) * N_DIM + gn] = make_int2(c2, c3);
            lmax = max(lmax, abs(c0));
            lmax = max(lmax, abs(c1));
            lmax = max(lmax, abs(c2));
            lmax = max(lmax, abs(c3));
        }
    }
#pragma unroll
    for (int o = 16; o > 0; o >>= 1) lmax = max(lmax, __shfl_xor_sync(0xffffffffu, lmax, o));
    if (lane == 0) atomicMax(&s_bmax, lmax);
    __syncthreads();
    if (tid == 0) atomicMax(&g_max, s_bmax);
}

// ----------------------------------------------------------------------------
// eff shift from the global max. Matches reference float32->ceil(log2) exactly
// by extracting the exponent/mantissa of float32(m): for f = 2^e * 1.frac,
// ceil(log2(f)) = e + (frac != 0).
__device__ __forceinline__ int compute_eff() {
    int m = g_max;
    if (m == 0) return 0;
    float mf = (float)m;  // round-nearest, same as numpy .astype(float32)
    unsigned bits = __float_as_uint(mf);
    int e  = (int)((bits >> 23) & 0xff) - 127;
    int bw = e + ((bits & 0x7fffffu) ? 1 : 0);
    int shift = bw - BITWIDTH;
    return shift > 1 ? shift : (shift == 1 ? 2 : 0);
}

__device__ __forceinline__ int psto_one(int x, int s) {
    int rt   = x >> s;                 // floor-divide by 2^s
    int prob = x & ((1 << s) - 1);     // non-negative remainder == |x - rt*2^s|
    int h    = s >> 1;
    int qp   = prob >> h;
    int prn  = prob & ((1 << h) - 1);
    if (s & 1) prn <<= 1;
    int sgn = (x > 0) - (x < 0);
    int dec = (qp <= prn) ? 0 : sgn;
    int o = rt + dec;
    o = o > 127 ? 127 : (o < -127 ? -127 : o);
    return o;
}

__global__ void __launch_bounds__(256) epilogue_kernel(float* __restrict__ out) {
    const int eff = compute_eff();
    size_t i = (size_t)blockIdx.x * blockDim.x + threadIdx.x;  // 4 elems/thread
    int4 v = ((const int4*)g_C32)[i];
    float4 o;
    if (eff > 0) {
        o.x = (float)psto_one(v.x, eff);
        o.y = (float)psto_one(v.y, eff);
        o.z = (float)psto_one(v.z, eff);
        o.w = (float)psto_one(v.w, eff);
    } else {
        // plain wrapping int8 cast path
        o.x = (float)(int8_t)(v.x);
        o.y = (float)(int8_t)(v.y);
        o.z = (float)(int8_t)(v.z);
        o.w = (float)(int8_t)(v.w);
    }
    ((float4*)out)[i] = o;
}

__global__ void tail_kernel(float* __restrict__ out, long long start, long long count,
                            const int* __restrict__ e1, const int* __restrict__ e2) {
    int eff = compute_eff();
    int8_t ev = (int8_t)(e1[0] + e2[0] + eff);
    for (long long i = threadIdx.x; i < count; i += blockDim.x)
        out[start + i] = (float)ev;
}

// ----------------------------------------------------------------------------
extern "C" void kernel_launch(void* const* d_in, const int* in_sizes, int n_in,
                              void* d_out, int out_size) {
    const int* act   = (const int*)d_in[0];
    const int* expin = (const int*)d_in[1];
    const int* wgt   = (const int*)d_in[2];
    const int* wexp  = (const int*)d_in[3];
    float* out = (float*)d_out;

    (void)in_sizes; (void)n_in;

    cudaFuncSetAttribute(gemm_s8_kernel, cudaFuncAttributeMaxDynamicSharedMemorySize,
                         4 * BM * BK);  // 64 KB

    zero_max_kernel<<<1, 32>>>();

    {
        int n16 = (int)(((size_t)M_DIM * K_DIM) / 16);  // 2097152
        pack_a_kernel<<<n16 / 256, 256>>>(act, n16);
    }
    {
        int n16 = (int)(((size_t)N_DIM * K_DIM) / 16);  // 1048576
        pack_b_kernel<<<n16 / 256, 256>>>(wgt, n16);
    }

    dim3 grid(N_DIM / BN, M_DIM / BM);  // (32, 64)
    gemm_s8_kernel<<<grid, 256, 4 * BM * BK>>>();

    {
        long long total = (long long)M_DIM * N_DIM;  // 33554432
        int blocks = (int)(total / 4 / 256);         // 32768
        epilogue_kernel<<<blocks, 256>>>(out);
        long long tail = (long long)out_size - total;
        if (tail > 0) tail_kernel<<<1, 32>>>(out, total, tail, expin, wexp);
    }
}

// round 5
// speedup vs baseline: 1.4092x; 1.4092x over previous
#include <cuda_runtime.h>
#include <cstdint>

// ============================================================================
// TiLinear hybrid: int8 GEMM (8192x4096x4096) split across BOTH pipes:
//   warps 0-7 : mma.sync m16n8k32 IMMA over k-tiles [0,18)
//   warps 8-15: dp4a (fma pipe) over k-tiles [18,32)
// Each group has its own 3-stage cp.async.bulk + mbarrier pipeline.
// Partials combined through smem; global max; psto requantize epilogue.
// Race fix vs R4: tensor group barrier (bar.sync 4) before repurposing the
// tensor pipeline smem as the partial-sum buffer.
// ============================================================================

#define M_DIM 8192
#define N_DIM 4096
#define K_DIM 4096
#define BITWIDTH 7

#define KTILES 32
#define NKT_T 18               // tensor-group k-tiles
#define NKT_D (KTILES - NKT_T) // dp4a-group k-tiles
#define TILE_BYTES 16384       // one 128x128 int8 tile
#define STAGE_BYTES 32768      // A tile + B tile
#define NST 3
#define TPOOL_OFF 0
#define DPOOL_OFF (NST * STAGE_BYTES)            // 98304
#define CTRL_OFF  (2 * NST * STAGE_BYTES)        // 196608
#define SMEM_DYN  (CTRL_OFF + 128)

__device__ __align__(128) int8_t g_A8[(size_t)M_DIM * K_DIM];   // 32 MB
__device__ __align__(128) int8_t g_B8[(size_t)N_DIM * K_DIM];   // 16 MB
__device__ __align__(16)  int    g_C32[(size_t)M_DIM * N_DIM];  // 128 MB
__device__ int g_max;

// ----------------------------------------------------------------------------
__global__ void zero_max_kernel() {
    if (threadIdx.x == 0) g_max = 0;
}

// A tiles: block = kt*64 + (m>>7), 128x128, SW-chunk-XOR pre-swizzled.
__global__ void __launch_bounds__(256) pack_a_kernel(const int* __restrict__ src) {
    unsigned i = blockIdx.x * 256u + threadIdx.x;   // 2^21 threads
    unsigned lc = i & 7u;
    unsigned m  = (i >> 3) & 8191u;
    unsigned kt = i >> 16;
    const int4* s = (const int4*)(src + (size_t)m * K_DIM + kt * 128 + lc * 16);
    uint32_t w[4];
#pragma unroll
    for (int j = 0; j < 4; ++j) {
        int4 v = s[j];
        w[j] = (uint32_t)(v.x & 0xff) | ((uint32_t)(v.y & 0xff) << 8) |
               ((uint32_t)(v.z & 0xff) << 16) | ((uint32_t)(v.w & 0xff) << 24);
    }
    unsigned lr = m & 127u;
    size_t base = (size_t)(kt * 64 + (m >> 7)) * TILE_BYTES;
    size_t off  = base + lr * 128 + (((lc ^ lr) & 7u) << 4);
    *(uint4*)(g_A8 + off) = make_uint4(w[0], w[1], w[2], w[3]);
}

// B tiles: block = kt*32 + (n>>7), 128x128.
__global__ void __launch_bounds__(256) pack_b_kernel(const int* __restrict__ src) {
    unsigned i = blockIdx.x * 256u + threadIdx.x;   // 2^20 threads
    unsigned lc = i & 7u;
    unsigned n  = (i >> 3) & 4095u;
    unsigned kt = i >> 15;
    const int4* s = (const int4*)(src + (size_t)n * K_DIM + kt * 128 + lc * 16);
    uint32_t w[4];
#pragma unroll
    for (int j = 0; j < 4; ++j) {
        int4 v = s[j];
        w[j] = (uint32_t)(v.x & 0xff) | ((uint32_t)(v.y & 0xff) << 8) |
               ((uint32_t)(v.z & 0xff) << 16) | ((uint32_t)(v.w & 0xff) << 24);
    }
    unsigned lr = n & 127u;
    size_t base = (size_t)(kt * 32 + (n >> 7)) * TILE_BYTES;
    size_t off  = base + lr * 128 + (((lc ^ lr) & 7u) << 4);
    *(uint4*)(g_B8 + off) = make_uint4(w[0], w[1], w[2], w[3]);
}

// ----------------------------------------------------------------------------
__device__ __forceinline__ void mbar_init(uint32_t a, uint32_t cnt) {
    asm volatile("mbarrier.init.shared.b64 [%0], %1;" :: "r"(a), "r"(cnt) : "memory");
}
__device__ __forceinline__ void mbar_expect_tx(uint32_t a, uint32_t bytes) {
    asm volatile("mbarrier.arrive.expect_tx.shared.b64 _, [%0], %1;"
                 :: "r"(a), "r"(bytes) : "memory");
}
__device__ __forceinline__ void mbar_arrive(uint32_t a) {
    asm volatile("mbarrier.arrive.shared.b64 _, [%0];" :: "r"(a) : "memory");
}
__device__ __forceinline__ void mbar_wait(uint32_t a, uint32_t parity) {
    asm volatile(
        "{\n\t.reg .pred P;\n\t"
        "WAIT_%=:\n\t"
        "mbarrier.try_wait.parity.acquire.cta.shared::cta.b64 P, [%0], %1, 0x989680;\n\t"
        "@P bra.uni DONE_%=;\n\t"
        "bra.uni WAIT_%=;\n\t"
        "DONE_%=:\n\t}"
        :: "r"(a), "r"(parity) : "memory");
}
__device__ __forceinline__ void bulk_g2s(uint32_t dst, const void* src,
                                         uint32_t bytes, uint32_t mbar) {
    asm volatile(
        "cp.async.bulk.shared::cluster.global.mbarrier::complete_tx::bytes "
        "[%0], [%1], %2, [%3];"
        :: "r"(dst), "l"(src), "r"(bytes), "r"(mbar) : "memory");
}
__device__ __forceinline__ uint32_t swz_off(uint32_t row, uint32_t chunk) {
    return row * 128u + (((chunk ^ row) & 7u) << 4);
}
__device__ __forceinline__ void bar_sync(int id, int cnt) {
    asm volatile("bar.sync %0, %1;" :: "r"(id), "r"(cnt) : "memory");
}

// fill one stage: A tile + B tile -> smem_dst, completion on mbar.
__device__ __forceinline__ void fill_stage(uint32_t smem_dst, uint32_t mbar,
                                           int kt, int by, int bx) {
    mbar_expect_tx(mbar, STAGE_BYTES);
    bulk_g2s(smem_dst, g_A8 + (size_t)(kt * 64 + by) * TILE_BYTES, TILE_BYTES, mbar);
    bulk_g2s(smem_dst + TILE_BYTES, g_B8 + (size_t)(kt * 32 + bx) * TILE_BYTES,
             TILE_BYTES, mbar);
}

// ----------------------------------------------------------------------------
__global__ void __launch_bounds__(512, 1) gemm_hybrid_kernel() {
    extern __shared__ __align__(1024) int8_t smem[];
    __shared__ int s_bmax;
    const int tid  = threadIdx.x;
    const int lane = tid & 31;
    const int warp = tid >> 5;
    const uint32_t sbase = (uint32_t)__cvta_generic_to_shared(smem);
    const int bx = blockIdx.x;   // n tile 0..31
    const int by = blockIdx.y;   // m tile 0..63
    const int m0 = by * 128;
    const int n0 = bx * 128;

    // mbarriers: [pool][slot][full/empty]
    const uint32_t mb = sbase + CTRL_OFF;
    if (tid == 0) {
        s_bmax = 0;
#pragma unroll
        for (int p = 0; p < 2; ++p)
#pragma unroll
            for (int s = 0; s < NST; ++s) {
                mbar_init(mb + (p * NST + s) * 16 + 0, 1);    // full (tx-based)
                mbar_init(mb + (p * NST + s) * 16 + 8, 256);  // empty
            }
        asm volatile("fence.mbarrier_init.release.cluster;" ::: "memory");
    }
    __syncthreads();

    if (warp < 8) {
        // ==================== TENSOR GROUP (k-tiles 0..NKT_T) ====================
        const uint32_t pool = sbase + TPOOL_OFF;
        const int wm = warp >> 2, wn = warp & 3;
        int acc[4][4][4];
#pragma unroll
        for (int a = 0; a < 4; ++a)
#pragma unroll
            for (int b = 0; b < 4; ++b)
#pragma unroll
                for (int c = 0; c < 4; ++c) acc[a][b][c] = 0;

        if (tid == 0) {
#pragma unroll
            for (int f = 0; f < 2; ++f) {
                mbar_wait(mb + f * 16 + 8, 1);      // fresh: passes
                fill_stage(pool + f * STAGE_BYTES, mb + f * 16, f, by, bx);
            }
        }

#pragma unroll 1
        for (int k = 0; k < NKT_T; ++k) {
            const int slot = k % NST;
            if (tid == 0 && k + 2 < NKT_T) {
                int f = k + 2, fs = f % NST;
                mbar_wait(mb + fs * 16 + 8, ((f / NST) & 1) ^ 1);
                fill_stage(pool + fs * STAGE_BYTES, mb + fs * 16, f, by, bx);
            }
            mbar_wait(mb + slot * 16, (k / NST) & 1);

            const int8_t* sa = smem + TPOOL_OFF + slot * STAGE_BYTES;
            const int8_t* sb = sa + TILE_BYTES;
#pragma unroll
            for (int ks = 0; ks < 4; ++ks) {
                uint32_t afr[4][4];
#pragma unroll
                for (int mi = 0; mi < 4; ++mi) {
                    int r = wm * 64 + mi * 16 + (lane & 15);
                    int c = ks * 2 + (lane >> 4);
                    uint32_t addr = (uint32_t)__cvta_generic_to_shared(sa + swz_off(r, c));
                    asm volatile(
                        "ldmatrix.sync.aligned.m8n8.x4.shared.b16 {%0,%1,%2,%3}, [%4];\n"
                        : "=r"(afr[mi][0]), "=r"(afr[mi][1]),
                          "=r"(afr[mi][2]), "=r"(afr[mi][3])
                        : "r"(addr));
                }
                uint32_t bfr[4][2];
#pragma unroll
                for (int ni = 0; ni < 4; ++ni) {
                    int r = wn * 32 + ni * 8 + (lane & 7);
                    int c = ks * 2 + ((lane >> 3) & 1);
                    uint32_t addr = (uint32_t)__cvta_generic_to_shared(sb + swz_off(r, c));
                    asm volatile(
                        "ldmatrix.sync.aligned.m8n8.x2.shared.b16 {%0,%1}, [%2];\n"
                        : "=r"(bfr[ni][0]), "=r"(bfr[ni][1])
                        : "r"(addr));
                }
#pragma unroll
                for (int mi = 0; mi < 4; ++mi)
#pragma unroll
                    for (int ni = 0; ni < 4; ++ni) {
                        asm volatile(
                            "mma.sync.aligned.m16n8k32.row.col.s32.s8.s8.s32 "
                            "{%0,%1,%2,%3}, {%4,%5,%6,%7}, {%8,%9}, {%0,%1,%2,%3};\n"
                            : "+r"(acc[mi][ni][0]), "+r"(acc[mi][ni][1]),
                              "+r"(acc[mi][ni][2]), "+r"(acc[mi][ni][3])
                            : "r"(afr[mi][0]), "r"(afr[mi][1]),
                              "r"(afr[mi][2]), "r"(afr[mi][3]),
                              "r"(bfr[ni][0]), "r"(bfr[ni][1]));
                    }
            }
            mbar_arrive(mb + slot * 16 + 8);
        }

        // RACE FIX: all tensor warps must finish consuming every pipeline slot
        // before this smem region is repurposed as the partial-sum buffer.
        bar_sync(4, 256);

        // write tensor partials to smem [0,64KB) (t-pool fully consumed)
        int* cs = (int*)smem;
#pragma unroll
        for (int mi = 0; mi < 4; ++mi)
#pragma unroll
            for (int ni = 0; ni < 4; ++ni) {
                int r = wm * 64 + mi * 16 + (lane >> 2);
                int c = wn * 32 + ni * 8 + (lane & 3) * 2;
                *(int2*)&cs[r * 128 + c] = make_int2(acc[mi][ni][0], acc[mi][ni][1]);
                *(int2*)&cs[(r + 8) * 128 + c] = make_int2(acc[mi][ni][2], acc[mi][ni][3]);
            }
        bar_sync(3, 512);
    } else {
        // ==================== DP4A GROUP (k-tiles NKT_T..32) ====================
        const uint32_t pool = sbase + DPOOL_OFF;
        const uint32_t mbd  = mb + NST * 16;
        const int wd = warp - 8;
        const int mg = lane >> 4;        // 0..1
        const int ng = lane & 15;        // 0..15
        const int rowA0 = 16 * wd + 8 * mg;

        int accD[64];
#pragma unroll
        for (int j = 0; j < 64; ++j) accD[j] = 0;

        if (tid == 256) {
#pragma unroll
            for (int f = 0; f < 2; ++f) {
                mbar_wait(mbd + f * 16 + 8, 1);
                fill_stage(pool + f * STAGE_BYTES, mbd + f * 16, NKT_T + f, by, bx);
            }
        }

#pragma unroll 1
        for (int k = 0; k < NKT_D; ++k) {
            const int slot = k % NST;
            if (tid == 256 && k + 2 < NKT_D) {
                int f = k + 2, fs = f % NST;
                mbar_wait(mbd + fs * 16 + 8, ((f / NST) & 1) ^ 1);
                fill_stage(pool + fs * STAGE_BYTES, mbd + fs * 16, NKT_T + f, by, bx);
            }
            mbar_wait(mbd + slot * 16, (k / NST) & 1);

            const int8_t* sa = smem + DPOOL_OFF + slot * STAGE_BYTES;
            const int8_t* sb = sa + TILE_BYTES;
#pragma unroll 1
            for (int cc = 0; cc < 8; ++cc) {
                const int ch = (cc + ng) & 7;          // lane-rotated k-chunk
                int4 a[8];
#pragma unroll
                for (int i = 0; i < 8; ++i)
                    a[i] = *(const int4*)(sa + (rowA0 + i) * 128 + ((ch ^ i) << 4));
#pragma unroll
                for (int nj = 0; nj < 8; ++nj) {
                    int4 b = *(const int4*)(sb + (8 * ng + nj) * 128 + ((ch ^ nj) << 4));
#pragma unroll
                    for (int i = 0; i < 8; ++i) {
                        int t = __dp4a(a[i].x, b.x, accD[i * 8 + nj]);
                        t = __dp4a(a[i].y, b.y, t);
                        t = __dp4a(a[i].z, b.z, t);
                        accD[i * 8 + nj] = __dp4a(a[i].w, b.w, t);
                    }
                }
            }
            mbar_arrive(mbd + slot * 16 + 8);
        }

        bar_sync(3, 512);
        // combine with tensor partials from smem, reduce max, store C32
        const int* cs = (const int*)smem;
        int lmax = 0;
#pragma unroll
        for (int i = 0; i < 8; ++i) {
            int r = rowA0 + i;
            int4 p0 = *(const int4*)&cs[r * 128 + 8 * ng];
            int4 p1 = *(const int4*)&cs[r * 128 + 8 * ng + 4];
            int v0 = p0.x + accD[i * 8 + 0];
            int v1 = p0.y + accD[i * 8 + 1];
            int v2 = p0.z + accD[i * 8 + 2];
            int v3 = p0.w + accD[i * 8 + 3];
            int v4 = p1.x + accD[i * 8 + 4];
            int v5 = p1.y + accD[i * 8 + 5];
            int v6 = p1.z + accD[i * 8 + 6];
            int v7 = p1.w + accD[i * 8 + 7];
            lmax = max(lmax, abs(v0)); lmax = max(lmax, abs(v1));
            lmax = max(lmax, abs(v2)); lmax = max(lmax, abs(v3));
            lmax = max(lmax, abs(v4)); lmax = max(lmax, abs(v5));
            lmax = max(lmax, abs(v6)); lmax = max(lmax, abs(v7));
            int* dst = g_C32 + (size_t)(m0 + r) * N_DIM + n0 + 8 * ng;
            *(int4*)dst       = make_int4(v0, v1, v2, v3);
            *(int4*)(dst + 4) = make_int4(v4, v5, v6, v7);
        }
#pragma unroll
        for (int o = 16; o > 0; o >>= 1)
            lmax = max(lmax, __shfl_xor_sync(0xffffffffu, lmax, o));
        if (lane == 0) atomicMax(&s_bmax, lmax);
        bar_sync(2, 256);
        if (tid == 256) atomicMax(&g_max, s_bmax);
    }
}

// ----------------------------------------------------------------------------
__device__ __forceinline__ int compute_eff() {
    int m = g_max;
    if (m == 0) return 0;
    float mf = (float)m;
    unsigned bits = __float_as_uint(mf);
    int e  = (int)((bits >> 23) & 0xff) - 127;
    int bw = e + ((bits & 0x7fffffu) ? 1 : 0);
    int shift = bw - BITWIDTH;
    return shift > 1 ? shift : (shift == 1 ? 2 : 0);
}

__device__ __forceinline__ int psto_one(int x, int s) {
    int rt   = x >> s;
    int prob = x & ((1 << s) - 1);
    int h    = s >> 1;
    int qp   = prob >> h;
    int prn  = prob & ((1 << h) - 1);
    if (s & 1) prn <<= 1;
    int sgn = (x > 0) - (x < 0);
    int dec = (qp <= prn) ? 0 : sgn;
    int o = rt + dec;
    o = o > 127 ? 127 : (o < -127 ? -127 : o);
    return o;
}

__global__ void __launch_bounds__(256) epilogue_kernel(float* __restrict__ out) {
    const int eff = compute_eff();
    size_t i = (size_t)blockIdx.x * blockDim.x + threadIdx.x;
    int4 v = ((const int4*)g_C32)[i];
    float4 o;
    if (eff > 0) {
        o.x = (float)psto_one(v.x, eff);
        o.y = (float)psto_one(v.y, eff);
        o.z = (float)psto_one(v.z, eff);
        o.w = (float)psto_one(v.w, eff);
    } else {
        o.x = (float)(int8_t)(v.x);
        o.y = (float)(int8_t)(v.y);
        o.z = (float)(int8_t)(v.z);
        o.w = (float)(int8_t)(v.w);
    }
    ((float4*)out)[i] = o;
}

__global__ void tail_kernel(float* __restrict__ out, long long start, long long count,
                            const int* __restrict__ e1, const int* __restrict__ e2) {
    int eff = compute_eff();
    int8_t ev = (int8_t)(e1[0] + e2[0] + eff);
    for (long long i = threadIdx.x; i < count; i += blockDim.x)
        out[start + i] = (float)ev;
}

// ----------------------------------------------------------------------------
extern "C" void kernel_launch(void* const* d_in, const int* in_sizes, int n_in,
                              void* d_out, int out_size) {
    const int* act   = (const int*)d_in[0];
    const int* expin = (const int*)d_in[1];
    const int* wgt   = (const int*)d_in[2];
    const int* wexp  = (const int*)d_in[3];
    float* out = (float*)d_out;
    (void)in_sizes; (void)n_in;

    cudaFuncSetAttribute(gemm_hybrid_kernel,
                         cudaFuncAttributeMaxDynamicSharedMemorySize, SMEM_DYN);

    zero_max_kernel<<<1, 32>>>();
    pack_a_kernel<<<8192, 256>>>(act);
    pack_b_kernel<<<4096, 256>>>(wgt);

    dim3 grid(N_DIM / 128, M_DIM / 128);   // (32, 64)
    gemm_hybrid_kernel<<<grid, 512, SMEM_DYN>>>();

    long long total = (long long)M_DIM * N_DIM;
    epilogue_kernel<<<(int)(total / 4 / 256), 256>>>(out);
    long long tail = (long long)out_size - total;
    if (tail > 0) tail_kernel<<<1, 32>>>(out, total, tail, expin, wexp);
}

// round 7
// speedup vs baseline: 1.5010x; 1.0651x over previous
#include <cuda_runtime.h>
#include <cstdint>

// ============================================================================
// TiLinear hybrid v2.1 (persistent): int8 GEMM (8192x4096x4096) on BOTH pipes.
//   warps 0-7 : mma.sync m16n8k32 IMMA, k-tiles [0,17)   (3-stage ring, +2 la)
//   warps 8-15: dp4a on the fma pipe,  k-tiles [17,32)   (2-stage ring, +1 la)
// 148 persistent CTAs loop over 2048 output tiles; rings run continuously
// across tiles. Dedicated smem partial buffer; combine + C32 store + max
// reduce overlap the NEXT tile's tensor mainloop.
// Deadlock fix vs R6: dp4a lookahead reduced to +1 (2-stage ring cannot
// support +2: fill(k+2) targets the slot consumed at step k).
// ============================================================================

#define M_DIM 8192
#define N_DIM 4096
#define K_DIM 4096
#define BITWIDTH 7

#define NTILES_TOTAL 2048
#define GRID_P 148

#define KTILES 32
#define NKT_T 17
#define NKT_D (KTILES - NKT_T)   // 15
#define TILE_BYTES 16384          // 128x128 int8
#define STAGE_BYTES 32768         // A tile + B tile
#define NST_T 3
#define NST_D 2
#define TPOOL_OFF 0
#define DPOOL_OFF (NST_T * STAGE_BYTES)                  // 98304
#define PART_OFF  (DPOOL_OFF + NST_D * STAGE_BYTES)      // 163840
#define CTRL_OFF  (PART_OFF + 65536)                     // 229376
#define SMEM_DYN  (CTRL_OFF + 128)                       // 229504

__device__ __align__(128) int8_t g_A8[(size_t)M_DIM * K_DIM];   // 32 MB
__device__ __align__(128) int8_t g_B8[(size_t)N_DIM * K_DIM];   // 16 MB
__device__ __align__(16)  int    g_C32[(size_t)M_DIM * N_DIM];  // 128 MB
__device__ int g_max;

// ----------------------------------------------------------------------------
__global__ void zero_max_kernel() {
    if (threadIdx.x == 0) g_max = 0;
}

// A tiles: block = kt*64 + (m>>7); 128x128; chunk-XOR swizzled rows.
__global__ void __launch_bounds__(256) pack_a_kernel(const int* __restrict__ src) {
    unsigned i = blockIdx.x * 256u + threadIdx.x;
    unsigned lc = i & 7u;
    unsigned m  = (i >> 3) & 8191u;
    unsigned kt = i >> 16;
    const int4* s = (const int4*)(src + (size_t)m * K_DIM + kt * 128 + lc * 16);
    uint32_t w[4];
#pragma unroll
    for (int j = 0; j < 4; ++j) {
        int4 v = s[j];
        w[j] = (uint32_t)(v.x & 0xff) | ((uint32_t)(v.y & 0xff) << 8) |
               ((uint32_t)(v.z & 0xff) << 16) | ((uint32_t)(v.w & 0xff) << 24);
    }
    unsigned lr = m & 127u;
    size_t base = (size_t)(kt * 64 + (m >> 7)) * TILE_BYTES;
    size_t off  = base + lr * 128 + (((lc ^ lr) & 7u) << 4);
    *(uint4*)(g_A8 + off) = make_uint4(w[0], w[1], w[2], w[3]);
}

// B tiles: block = kt*32 + (n>>7).
__global__ void __launch_bounds__(256) pack_b_kernel(const int* __restrict__ src) {
    unsigned i = blockIdx.x * 256u + threadIdx.x;
    unsigned lc = i & 7u;
    unsigned n  = (i >> 3) & 4095u;
    unsigned kt = i >> 15;
    const int4* s = (const int4*)(src + (size_t)n * K_DIM + kt * 128 + lc * 16);
    uint32_t w[4];
#pragma unroll
    for (int j = 0; j < 4; ++j) {
        int4 v = s[j];
        w[j] = (uint32_t)(v.x & 0xff) | ((uint32_t)(v.y & 0xff) << 8) |
               ((uint32_t)(v.z & 0xff) << 16) | ((uint32_t)(v.w & 0xff) << 24);
    }
    unsigned lr = n & 127u;
    size_t base = (size_t)(kt * 32 + (n >> 7)) * TILE_BYTES;
    size_t off  = base + lr * 128 + (((lc ^ lr) & 7u) << 4);
    *(uint4*)(g_B8 + off) = make_uint4(w[0], w[1], w[2], w[3]);
}

// ----------------------------------------------------------------------------
__device__ __forceinline__ void mbar_init(uint32_t a, uint32_t cnt) {
    asm volatile("mbarrier.init.shared.b64 [%0], %1;" :: "r"(a), "r"(cnt) : "memory");
}
__device__ __forceinline__ void mbar_expect_tx(uint32_t a, uint32_t bytes) {
    asm volatile("mbarrier.arrive.expect_tx.shared.b64 _, [%0], %1;"
                 :: "r"(a), "r"(bytes) : "memory");
}
__device__ __forceinline__ void mbar_arrive(uint32_t a) {
    asm volatile("mbarrier.arrive.shared.b64 _, [%0];" :: "r"(a) : "memory");
}
__device__ __forceinline__ void mbar_wait(uint32_t a, uint32_t parity) {
    asm volatile(
        "{\n\t.reg .pred P;\n\t"
        "WAIT_%=:\n\t"
        "mbarrier.try_wait.parity.acquire.cta.shared::cta.b64 P, [%0], %1, 0x989680;\n\t"
        "@P bra.uni DONE_%=;\n\t"
        "bra.uni WAIT_%=;\n\t"
        "DONE_%=:\n\t}"
        :: "r"(a), "r"(parity) : "memory");
}
__device__ __forceinline__ void bulk_g2s(uint32_t dst, const void* src,
                                         uint32_t bytes, uint32_t mbar) {
    asm volatile(
        "cp.async.bulk.shared::cluster.global.mbarrier::complete_tx::bytes "
        "[%0], [%1], %2, [%3];"
        :: "r"(dst), "l"(src), "r"(bytes), "r"(mbar) : "memory");
}
__device__ __forceinline__ uint32_t swz_off(uint32_t row, uint32_t chunk) {
    return row * 128u + (((chunk ^ row) & 7u) << 4);
}
__device__ __forceinline__ void bar_sync(int id, int cnt) {
    asm volatile("bar.sync %0, %1;" :: "r"(id), "r"(cnt) : "memory");
}
__device__ __forceinline__ void fill_blocks(uint32_t dst, uint32_t mbar,
                                            int ablk, int bblk) {
    mbar_expect_tx(mbar, STAGE_BYTES);
    bulk_g2s(dst, g_A8 + (size_t)ablk * TILE_BYTES, TILE_BYTES, mbar);
    bulk_g2s(dst + TILE_BYTES, g_B8 + (size_t)bblk * TILE_BYTES, TILE_BYTES, mbar);
}

// ----------------------------------------------------------------------------
__global__ void __launch_bounds__(512, 1) gemm_persist_kernel() {
    extern __shared__ __align__(1024) int8_t smem[];
    __shared__ int s_bmax;
    const int tid  = threadIdx.x;
    const int lane = tid & 31;
    const int warp = tid >> 5;
    const int bid  = blockIdx.x;
    const int ntiles = (NTILES_TOTAL - 1 - bid) / GRID_P + 1;
    const uint32_t sbase = (uint32_t)__cvta_generic_to_shared(smem);
    const uint32_t mbT = sbase + CTRL_OFF;          // 3 pairs (full, empty)
    const uint32_t mbD = sbase + CTRL_OFF + 48;     // 2 pairs

    if (tid == 0) {
        s_bmax = 0;
#pragma unroll
        for (int s = 0; s < NST_T; ++s) {
            mbar_init(mbT + s * 16 + 0, 1);
            mbar_init(mbT + s * 16 + 8, 256);
        }
#pragma unroll
        for (int s = 0; s < NST_D; ++s) {
            mbar_init(mbD + s * 16 + 0, 1);
            mbar_init(mbD + s * 16 + 8, 256);
        }
        asm volatile("fence.mbarrier_init.release.cluster;" ::: "memory");
    }
    __syncthreads();

    if (warp < 8) {
        // ==================== TENSOR GROUP ====================
        const int wm = warp >> 2, wn = warp & 3;
        const int total = ntiles * NKT_T;
        int cs = 0, cp = 0;        // consumer cursor
        int ps = 0, pp = 1;        // producer cursor (fresh empty passes at 1)

        auto t_fill = [&](int f) {
            int li = f / NKT_T;
            int kt = f - li * NKT_T;
            int tile = bid + li * GRID_P;
            mbar_wait(mbT + ps * 16 + 8, pp);
            fill_blocks(sbase + TPOOL_OFF + ps * STAGE_BYTES, mbT + ps * 16,
                        kt * 64 + (tile >> 5), kt * 32 + (tile & 31));
            if (++ps == NST_T) { ps = 0; pp ^= 1; }
        };

        if (tid == 0) { t_fill(0); if (total > 1) t_fill(1); }

        for (int li = 0; li < ntiles; ++li) {
            int acc[4][4][4];
#pragma unroll
            for (int a = 0; a < 4; ++a)
#pragma unroll
                for (int b = 0; b < 4; ++b)
#pragma unroll
                    for (int c = 0; c < 4; ++c) acc[a][b][c] = 0;

#pragma unroll 1
            for (int k = 0; k < NKT_T; ++k) {
                if (tid == 0) {
                    int f = li * NKT_T + k + 2;
                    if (f < total) t_fill(f);
                }
                mbar_wait(mbT + cs * 16, cp);

                const int8_t* sa = smem + TPOOL_OFF + cs * STAGE_BYTES;
                const int8_t* sb = sa + TILE_BYTES;
#pragma unroll
                for (int ks = 0; ks < 4; ++ks) {
                    uint32_t afr[4][4];
#pragma unroll
                    for (int mi = 0; mi < 4; ++mi) {
                        int r = wm * 64 + mi * 16 + (lane & 15);
                        int c = ks * 2 + (lane >> 4);
                        uint32_t addr =
                            (uint32_t)__cvta_generic_to_shared(sa + swz_off(r, c));
                        asm volatile(
                            "ldmatrix.sync.aligned.m8n8.x4.shared.b16 "
                            "{%0,%1,%2,%3}, [%4];\n"
                            : "=r"(afr[mi][0]), "=r"(afr[mi][1]),
                              "=r"(afr[mi][2]), "=r"(afr[mi][3])
                            : "r"(addr));
                    }
                    uint32_t bfr[4][2];
#pragma unroll
                    for (int ni = 0; ni < 4; ++ni) {
                        int r = wn * 32 + ni * 8 + (lane & 7);
                        int c = ks * 2 + ((lane >> 3) & 1);
                        uint32_t addr =
                            (uint32_t)__cvta_generic_to_shared(sb + swz_off(r, c));
                        asm volatile(
                            "ldmatrix.sync.aligned.m8n8.x2.shared.b16 {%0,%1}, [%2];\n"
                            : "=r"(bfr[ni][0]), "=r"(bfr[ni][1])
                            : "r"(addr));
                    }
#pragma unroll
                    for (int mi = 0; mi < 4; ++mi)
#pragma unroll
                        for (int ni = 0; ni < 4; ++ni) {
                            asm volatile(
                                "mma.sync.aligned.m16n8k32.row.col.s32.s8.s8.s32 "
                                "{%0,%1,%2,%3}, {%4,%5,%6,%7}, {%8,%9}, {%0,%1,%2,%3};\n"
                                : "+r"(acc[mi][ni][0]), "+r"(acc[mi][ni][1]),
                                  "+r"(acc[mi][ni][2]), "+r"(acc[mi][ni][3])
                                : "r"(afr[mi][0]), "r"(afr[mi][1]),
                                  "r"(afr[mi][2]), "r"(afr[mi][3]),
                                  "r"(bfr[ni][0]), "r"(bfr[ni][1]));
                        }
                }
                mbar_arrive(mbT + cs * 16 + 8);
                if (++cs == NST_T) { cs = 0; cp ^= 1; }
            }

            // Y barrier: dp4a finished reading the previous tile's partials
            bar_sync(3, 512);
            int* pbuf = (int*)(smem + PART_OFF);
#pragma unroll
            for (int mi = 0; mi < 4; ++mi)
#pragma unroll
                for (int ni = 0; ni < 4; ++ni) {
                    int r = wm * 64 + mi * 16 + (lane >> 2);
                    int c = wn * 32 + ni * 8 + (lane & 3) * 2;
                    *(int2*)&pbuf[r * 128 + c] =
                        make_int2(acc[mi][ni][0], acc[mi][ni][1]);
                    *(int2*)&pbuf[(r + 8) * 128 + c] =
                        make_int2(acc[mi][ni][2], acc[mi][ni][3]);
                }
            // X barrier: partials ready for this tile
            bar_sync(3, 512);
        }
    } else {
        // ==================== DP4A GROUP ====================
        const int wd = warp - 8;
        const int mg = lane >> 4;
        const int ng = lane & 15;
        const int rowA0 = 16 * wd + 8 * mg;
        const int total = ntiles * NKT_D;
        int cs = 0, cp = 0;
        int ps = 0, pp = 1;
        int lmax = 0;

        auto d_fill = [&](int f) {
            int li = f / NKT_D;
            int kd = f - li * NKT_D;
            int tile = bid + li * GRID_P;
            mbar_wait(mbD + ps * 16 + 8, pp);
            fill_blocks(sbase + DPOOL_OFF + ps * STAGE_BYTES, mbD + ps * 16,
                        (NKT_T + kd) * 64 + (tile >> 5),
                        (NKT_T + kd) * 32 + (tile & 31));
            if (++ps == NST_D) { ps = 0; pp ^= 1; }
        };

        // DEADLOCK FIX: 2-stage ring -> prefill exactly ONE stage, +1 lookahead.
        if (tid == 256) d_fill(0);

        for (int li = 0; li < ntiles; ++li) {
            const int tile = bid + li * GRID_P;
            const int m0 = (tile >> 5) * 128;
            const int n0 = (tile & 31) * 128;

            int accD[64];
#pragma unroll
            for (int j = 0; j < 64; ++j) accD[j] = 0;

#pragma unroll 1
            for (int k = 0; k < NKT_D; ++k) {
                if (tid == 256) {
                    int f = li * NKT_D + k + 1;   // +1 lookahead only
                    if (f < total) d_fill(f);
                }
                mbar_wait(mbD + cs * 16, cp);

                const int8_t* sa = smem + DPOOL_OFF + cs * STAGE_BYTES;
                const int8_t* sb = sa + TILE_BYTES;
#pragma unroll 1
                for (int cc = 0; cc < 8; ++cc) {
                    const int ch = (cc + ng) & 7;
                    int4 a[8];
#pragma unroll
                    for (int i = 0; i < 8; ++i)
                        a[i] = *(const int4*)(sa + (rowA0 + i) * 128 + ((ch ^ i) << 4));
#pragma unroll
                    for (int nj = 0; nj < 8; ++nj) {
                        int4 b = *(const int4*)(sb + (8 * ng + nj) * 128 +
                                                ((ch ^ nj) << 4));
#pragma unroll
                        for (int i = 0; i < 8; ++i) {
                            int t = __dp4a(a[i].x, b.x, accD[i * 8 + nj]);
                            t = __dp4a(a[i].y, b.y, t);
                            t = __dp4a(a[i].z, b.z, t);
                            accD[i * 8 + nj] = __dp4a(a[i].w, b.w, t);
                        }
                    }
                }
                mbar_arrive(mbD + cs * 16 + 8);
                if (++cs == NST_D) { cs = 0; cp ^= 1; }
            }

            bar_sync(3, 512);   // Y
            bar_sync(3, 512);   // X: partials ready
            // combine (overlaps tensor's next-tile mainloop)
            const int* pbuf = (const int*)(smem + PART_OFF);
#pragma unroll
            for (int i = 0; i < 8; ++i) {
                int r = rowA0 + i;
                int4 p0 = *(const int4*)&pbuf[r * 128 + 8 * ng];
                int4 p1 = *(const int4*)&pbuf[r * 128 + 8 * ng + 4];
                int v0 = p0.x + accD[i * 8 + 0];
                int v1 = p0.y + accD[i * 8 + 1];
                int v2 = p0.z + accD[i * 8 + 2];
                int v3 = p0.w + accD[i * 8 + 3];
                int v4 = p1.x + accD[i * 8 + 4];
                int v5 = p1.y + accD[i * 8 + 5];
                int v6 = p1.z + accD[i * 8 + 6];
                int v7 = p1.w + accD[i * 8 + 7];
                lmax = max(lmax, abs(v0)); lmax = max(lmax, abs(v1));
                lmax = max(lmax, abs(v2)); lmax = max(lmax, abs(v3));
                lmax = max(lmax, abs(v4)); lmax = max(lmax, abs(v5));
                lmax = max(lmax, abs(v6)); lmax = max(lmax, abs(v7));
                int* dst = g_C32 + (size_t)(m0 + r) * N_DIM + n0 + 8 * ng;
                *(int4*)dst       = make_int4(v0, v1, v2, v3);
                *(int4*)(dst + 4) = make_int4(v4, v5, v6, v7);
            }
        }

#pragma unroll
        for (int o = 16; o > 0; o >>= 1)
            lmax = max(lmax, __shfl_xor_sync(0xffffffffu, lmax, o));
        if (lane == 0) atomicMax(&s_bmax, lmax);
        bar_sync(2, 256);
        if (tid == 256) atomicMax(&g_max, s_bmax);
    }
}

// ----------------------------------------------------------------------------
__device__ __forceinline__ int compute_eff() {
    int m = g_max;
    if (m == 0) return 0;
    float mf = (float)m;
    unsigned bits = __float_as_uint(mf);
    int e  = (int)((bits >> 23) & 0xff) - 127;
    int bw = e + ((bits & 0x7fffffu) ? 1 : 0);
    int shift = bw - BITWIDTH;
    return shift > 1 ? shift : (shift == 1 ? 2 : 0);
}

__device__ __forceinline__ int psto_one(int x, int s) {
    int rt   = x >> s;
    int prob = x & ((1 << s) - 1);
    int h    = s >> 1;
    int qp   = prob >> h;
    int prn  = prob & ((1 << h) - 1);
    if (s & 1) prn <<= 1;
    int sgn = (x > 0) - (x < 0);
    int dec = (qp <= prn) ? 0 : sgn;
    int o = rt + dec;
    o = o > 127 ? 127 : (o < -127 ? -127 : o);
    return o;
}

__global__ void __launch_bounds__(256) epilogue_kernel(float* __restrict__ out) {
    const int eff = compute_eff();
    size_t i = (size_t)blockIdx.x * blockDim.x + threadIdx.x;
    int4 v = ((const int4*)g_C32)[i];
    float4 o;
    if (eff > 0) {
        o.x = (float)psto_one(v.x, eff);
        o.y = (float)psto_one(v.y, eff);
        o.z = (float)psto_one(v.z, eff);
        o.w = (float)psto_one(v.w, eff);
    } else {
        o.x = (float)(int8_t)(v.x);
        o.y = (float)(int8_t)(v.y);
        o.z = (float)(int8_t)(v.z);
        o.w = (float)(int8_t)(v.w);
    }
    ((float4*)out)[i] = o;
}

__global__ void tail_kernel(float* __restrict__ out, long long start, long long count,
                            const int* __restrict__ e1, const int* __restrict__ e2) {
    int eff = compute_eff();
    int8_t ev = (int8_t)(e1[0] + e2[0] + eff);
    for (long long i = threadIdx.x; i < count; i += blockDim.x)
        out[start + i] = (float)ev;
}

// ----------------------------------------------------------------------------
extern "C" void kernel_launch(void* const* d_in, const int* in_sizes, int n_in,
                              void* d_out, int out_size) {
    const int* act   = (const int*)d_in[0];
    const int* expin = (const int*)d_in[1];
    const int* wgt   = (const int*)d_in[2];
    const int* wexp  = (const int*)d_in[3];
    float* out = (float*)d_out;
    (void)in_sizes; (void)n_in;

    cudaFuncSetAttribute(gemm_persist_kernel,
                         cudaFuncAttributeMaxDynamicSharedMemorySize, SMEM_DYN);

    zero_max_kernel<<<1, 32>>>();
    pack_a_kernel<<<8192, 256>>>(act);
    pack_b_kernel<<<4096, 256>>>(wgt);

    gemm_persist_kernel<<<GRID_P, 512, SMEM_DYN>>>();

    long long total = (long long)M_DIM * N_DIM;
    epilogue_kernel<<<(int)(total / 4 / 256), 256>>>(out);
    long long tail = (long long)out_size - total;
    if (tail > 0) tail_kernel<<<1, 32>>>(out, total, tail, expin, wexp);
}